// round 17
// baseline (speedup 1.0000x reference)
#include <cuda_runtime.h>
#include <cuda_fp16.h>
#include <cstdint>
#include <cstddef>

// 2-layer LSTM, T=1024, B=16, I=H=1024.
// Merged-v4: one persistent kernel, layers pipelined AND phase-split:
// f0 (h0 ready) released right after the L0 cell, f1 (h1 ready) after the
// L1 cell. The f0 recurrence cycle excludes all L1 work; warps 4-7 overlap
// L1 GEMMs with warps 0-3's L0 cell. L0 weights in SMEM, L1 in registers.
#define T_   1024
#define B_   16
#define H_   1024
#define NCTA 128
#define NTHR 256
#define FLAG_STRIDE 32                 // one flag per 128B line
#define WFRAG_L (NCTA*128*4*32*2)      // u32 per layer = 4,194,304
#define XFRAG_T 8192                   // u32 per timestep A-frag (32 KB)
#define HFRAG_SZ XFRAG_T
#define RED_STRIDE 576                 // 16 b-rows * 36 floats
// smem u32: s_x[8192] | s_wx0[16384] | s_wh0[16384] | s_red[16*576]f
#define SMEM_U32 (8192 + 16384 + 16384 + 16*RED_STRIDE)
#define SMEM_BYTES (SMEM_U32*4)        // 200704 B

__device__ __align__(16) uint32_t g_wfrag[2][WFRAG_L];
__device__ __align__(16) uint32_t g_xfrag0[(size_t)T_*XFRAG_T];
__device__ __align__(16) uint32_t g_h0f[2*HFRAG_SZ];
__device__ __align__(16) uint32_t g_h1f[2*HFRAG_SZ];
__device__ __align__(128) unsigned g_f0[NCTA*FLAG_STRIDE];
__device__ __align__(128) unsigned g_f1[NCTA*FLAG_STRIDE];

// ---------------------------------------------------------------------------
__global__ void k_reset() {
    int i = blockIdx.x * blockDim.x + threadIdx.x;
    if (i < 2*HFRAG_SZ) { g_h0f[i] = 0u; g_h1f[i] = 0u; }
    if (i < NCTA*FLAG_STRIDE) { g_f0[i] = 0u; g_f1[i] = 0u; }
}

// B-frag layout for [Wih;Whh]: idx = (((c*128+kk)*4+nt)*32+lane)*2+p
// lane=4g+tq ; W row = nt*H + c*8 + g ; k = (kk&63)*16 + 2tq + 8p + {0,1}
// kk<64 -> Wih, kk>=64 -> Whh
__global__ void k_conv_w(const float* __restrict__ Wih0, const float* __restrict__ Whh0,
                         const float* __restrict__ Wih1, const float* __restrict__ Whh1) {
    int layer = blockIdx.y;
    const float* Wih = layer ? Wih1 : Wih0;
    const float* Whh = layer ? Whh1 : Whh0;
    int stride = gridDim.x * blockDim.x;
    for (int idx = blockIdx.x * blockDim.x + threadIdx.x; idx < WFRAG_L; idx += stride) {
        int p    = idx & 1;
        int lane = (idx >> 1) & 31;
        int nt   = (idx >> 6) & 3;
        int kk   = (idx >> 8) & 127;
        int c    = idx >> 15;
        int g = lane >> 2, tq = lane & 3;
        int row = nt * H_ + c * 8 + g;
        int kl  = (kk & 63) * 16 + tq * 2 + p * 8;
        const float2 v = *reinterpret_cast<const float2*>(
            (kk < 64 ? Wih : Whh) + (size_t)row * H_ + kl);
        __half2 hv = __floats2half2_rn(v.x, v.y);
        g_wfrag[layer][idx] = *reinterpret_cast<uint32_t*>(&hv);
    }
}

// A-frag layout for x: per-t idx = (kk*32+lane)*4 + r ; b = g + 8*(r&1) ;
// k = kk*16 + 2tq + 8*(r>>1) + {0,1}
__global__ void k_conv_x(const float* __restrict__ x) {
    size_t total = (size_t)T_ * XFRAG_T;
    size_t stride = (size_t)gridDim.x * blockDim.x;
    for (size_t idx = (size_t)blockIdx.x * blockDim.x + threadIdx.x; idx < total; idx += stride) {
        int it = (int)(idx >> 13);
        int r8 = (int)(idx & (XFRAG_T - 1));
        int kk   = r8 >> 7;
        int lane = (r8 >> 2) & 31;
        int r    = r8 & 3;
        int g = lane >> 2, tq = lane & 3;
        int b  = g + ((r & 1) << 3);
        int kb = kk * 16 + tq * 2 + ((r >> 1) << 3);
        const float2 v = *reinterpret_cast<const float2*>(
            x + ((size_t)it * B_ + b) * H_ + kb);
        __half2 hv = __floats2half2_rn(v.x, v.y);
        g_xfrag0[idx] = *reinterpret_cast<uint32_t*>(&hv);
    }
}

// ---------------------------------------------------------------------------
__device__ __forceinline__ float tanh_ap(float v) {
    float r;
    asm("tanh.approx.f32 %0, %1;" : "=f"(r) : "f"(v));
    return r;
}
__device__ __forceinline__ float sigmoid_ap(float v) {
    return fmaf(tanh_ap(0.5f * v), 0.5f, 0.5f);
}

__device__ __forceinline__ void cpa16(uint32_t dst, const void* src) {
    asm volatile("cp.async.cg.shared.global [%0], [%1], 16;" :: "r"(dst), "l"(src));
}
#define CP_COMMIT asm volatile("cp.async.commit_group;")
#define CP_WAIT0  asm volatile("cp.async.wait_group 0;")

__device__ __forceinline__ uint4 ldcg4(const uint4* p) {
    uint4 v;
    asm volatile("ld.global.cg.v4.u32 {%0,%1,%2,%3}, [%4];"
                 : "=r"(v.x), "=r"(v.y), "=r"(v.z), "=r"(v.w) : "l"(p));
    return v;
}
__device__ __forceinline__ unsigned ld_acq(const unsigned* p) {
    unsigned v;
    asm volatile("ld.acquire.gpu.global.u32 %0, [%1];" : "=r"(v) : "l"(p));
    return v;
}
__device__ __forceinline__ void st_release_u32(unsigned* p, unsigned v) {
    asm volatile("st.release.gpu.global.u32 [%0], %1;" :: "l"(p), "r"(v) : "memory");
}

__device__ __forceinline__ void mma16816(float* acc, const uint4& a, const uint2& b) {
    asm volatile(
        "mma.sync.aligned.m16n8k16.row.col.f32.f16.f16.f32 "
        "{%0,%1,%2,%3}, {%4,%5,%6,%7}, {%8,%9}, {%0,%1,%2,%3};\n"
        : "+f"(acc[0]), "+f"(acc[1]), "+f"(acc[2]), "+f"(acc[3])
        : "r"(a.x), "r"(a.y), "r"(a.z), "r"(a.w), "r"(b.x), "r"(b.y));
}

__global__ void __launch_bounds__(NTHR, 1)
k_lstm(const float* __restrict__ bih0, const float* __restrict__ bhh0,
       const float* __restrict__ bih1, const float* __restrict__ bhh1,
       float* __restrict__ out, float* __restrict__ nh, float* __restrict__ nc) {
    extern __shared__ uint32_t smem[];
    uint32_t* s_x   = smem;                     // 8192 u32 x A-frag
    uint32_t* s_wx0 = smem + 8192;              // L0 Wih (kk 0..63)
    uint32_t* s_wh0 = smem + 24576;             // L0 Whh (local kk 0..63)
    float*    s_red = (float*)(smem + 40960);   // 16 b-rows * 576

    uint32_t sbase;
    asm("{ .reg .u64 t; cvta.to.shared.u64 t, %1; cvt.u32.u64 %0, t; }"
        : "=r"(sbase) : "l"(smem));
    const uint32_t A_X = sbase;
    const uint32_t A_W = sbase + 8192u*4u;

    const int tid = threadIdx.x, warp = tid >> 5, lane = tid & 31;
    const int cblk = blockIdx.x;
    const int g = lane >> 2, tq = lane & 3;

    // ---- L1 weights -> registers
    uint2 bi1r[8][4], bh1r[8][4];
    {
        const uint32_t* wf1 = g_wfrag[1] + (size_t)cblk * 32768;
        #pragma unroll
        for (int j = 0; j < 8; j++) {
            #pragma unroll
            for (int nt = 0; nt < 4; nt++) {
                int kki = warp * 8 + j;
                int kkh = 64 + warp * 8 + j;
                bi1r[j][nt] = *(const uint2*)&wf1[((kki * 4 + nt) * 32 + lane) * 2];
                bh1r[j][nt] = *(const uint2*)&wf1[((kkh * 4 + nt) * 32 + lane) * 2];
            }
        }
    }

    // ---- prologue: L0 weights (128 KB) + x[0] -> smem
    {
        const uint4* w0 = (const uint4*)(g_wfrag[0] + (size_t)cblk * 32768);
        #pragma unroll
        for (int i = 0; i < 32; i++)
            cpa16(A_W + (tid + i*NTHR)*16u, w0 + tid + i*NTHR);
        const uint4* xs = (const uint4*)g_xfrag0;
        #pragma unroll
        for (int i = 0; i < 8; i++)
            cpa16(A_X + (tid + i*NTHR)*16u, xs + tid + i*NTHR);
        CP_COMMIT; CP_WAIT0;
    }

    // ---- cell state: warps 0-3 -> L0, warps 4-7 -> L1
    const int cl = tid >> 7;
    const int wg = tid & 127;
    const int b  = wg & 15;
    const int lu = wg >> 4;
    const int u  = cblk * 8 + lu;
    float cc = 0.f;
    float bs0, bs1, bs2, bs3;
    {
        const float* bi = cl ? bih1 : bih0;
        const float* bh = cl ? bhh1 : bhh0;
        bs0 = bi[u]        + bh[u];
        bs1 = bi[H_ + u]   + bh[H_ + u];
        bs2 = bi[2*H_ + u] + bh[2*H_ + u];
        bs3 = bi[3*H_ + u] + bh[3*H_ + u];
    }
    int h_a32;
    {
        int ue = u & ~1;
        int kl = ue & 15;
        int tq_ = (kl >> 1) & 3;
        int rr  = (b >> 3) + ((kl >> 3) << 1);
        int ln_ = ((b & 7) << 2) | tq_;
        h_a32 = ((ue >> 4) * 32 + ln_) * 4 + rr;
    }
    const int myflag = (warp * 16 + (lane & 15)) * FLAG_STRIDE;
    __syncthreads();

    #pragma unroll 1
    for (int s = 0; s <= T_; ++s) {
        // ===== phase 1: L0 x-GEMM (pre-poll; smem A and B) =====
        float acc0[4][4];
        #pragma unroll
        for (int nt = 0; nt < 4; nt++)
            #pragma unroll
            for (int j = 0; j < 4; j++) acc0[nt][j] = 0.f;
        #pragma unroll
        for (int j = 0; j < 8; j++) {
            int kk = warp * 8 + j;
            uint4 a = *(const uint4*)&s_x[(kk * 32 + lane) * 4];
            #pragma unroll
            for (int nt = 0; nt < 4; nt++) {
                uint2 bb = *(const uint2*)&s_wx0[((kk * 4 + nt) * 32 + lane) * 2];
                mma16816(acc0[nt], a, bb);
            }
        }

        // ===== phase 2: poll f0, ah0, L0 h-GEMM, L0 red =====
        if (s) {
            const unsigned tgt = (unsigned)s;
            for (;;) {
                unsigned v = ld_acq(&g_f0[myflag]);
                if (__all_sync(0xffffffffu, v >= tgt)) break;
            }
        }
        uint4 ah0[8];
        {
            const uint4* h0p = (const uint4*)(g_h0f + (size_t)(s & 1) * HFRAG_SZ);
            #pragma unroll
            for (int j = 0; j < 8; j++)
                ah0[j] = ldcg4(h0p + ((warp * 8 + j) * 32 + lane));
        }
        #pragma unroll
        for (int j = 0; j < 8; j++) {
            int kk = warp * 8 + j;
            #pragma unroll
            for (int nt = 0; nt < 4; nt++) {
                uint2 bb = *(const uint2*)&s_wh0[((kk * 4 + nt) * 32 + lane) * 2];
                mma16816(acc0[nt], ah0[j], bb);
            }
        }
        {
            float* rp = s_red + warp * RED_STRIDE;
            #pragma unroll
            for (int nt = 0; nt < 4; nt++) {
                int c0 = (tq * 2) * 4 + nt;
                int c1 = (tq * 2 + 1) * 4 + nt;
                rp[g * 36 + c0]       = acc0[nt][0];
                rp[g * 36 + c1]       = acc0[nt][1];
                rp[(g + 8) * 36 + c0] = acc0[nt][2];
                rp[(g + 8) * 36 + c1] = acc0[nt][3];
            }
        }
        asm volatile("bar.sync 2, 256;" ::: "memory");   // L0 red ready

        // ===== phase 3 (warps 0-3): L0 cell -> h0 -> release f0 =====
        float hv = 0.f;
        if (cl == 0) {
            if (s < T_) {
                float gi = bs0, gf = bs1, gg = bs2, go = bs3;
                const float* rb = s_red + b * 36 + lu * 4;
                #pragma unroll
                for (int w = 0; w < 8; w++) {
                    float4 v = *(const float4*)&rb[w * RED_STRIDE];
                    gi += v.x; gf += v.y; gg += v.z; go += v.w;
                }
                float fi = sigmoid_ap(gi);
                float ff = sigmoid_ap(gf);
                float fg = tanh_ap(gg);
                float fo = sigmoid_ap(go);
                cc = ff * cc + fi * fg;
                hv = fo * tanh_ap(cc);
                unsigned us = (unsigned)__half_as_ushort(__float2half_rn(hv));
                unsigned other = __shfl_xor_sync(0xffffffffu, us, 16);
                if (lane < 16)
                    g_h0f[(size_t)((s + 1) & 1) * HFRAG_SZ + h_a32] = us | (other << 16);
            }
            asm volatile("bar.sync 3, 128;" ::: "memory");
            if (tid == 0)
                st_release_u32(&g_f0[cblk * FLAG_STRIDE], (unsigned)(s + 1));
        }

        // ===== phase 4: L1 GEMMs (warps 4-7 start right after bar 2) =====
        float acc1[4][4];
        #pragma unroll
        for (int nt = 0; nt < 4; nt++)
            #pragma unroll
            for (int j = 0; j < 4; j++) acc1[nt][j] = 0.f;
        #pragma unroll
        for (int j = 0; j < 8; j++) {
            #pragma unroll
            for (int nt = 0; nt < 4; nt++) mma16816(acc1[nt], ah0[j], bi1r[j][nt]);
        }
        if (s) {
            const unsigned tgt = (unsigned)s;
            for (;;) {
                unsigned v = ld_acq(&g_f1[myflag]);
                if (__all_sync(0xffffffffu, v >= tgt)) break;
            }
        }
        {
            uint4 ah1[8];
            const uint4* h1p = (const uint4*)(g_h1f + (size_t)(s & 1) * HFRAG_SZ);
            #pragma unroll
            for (int j = 0; j < 8; j++)
                ah1[j] = ldcg4(h1p + ((warp * 8 + j) * 32 + lane));
            #pragma unroll
            for (int j = 0; j < 8; j++) {
                #pragma unroll
                for (int nt = 0; nt < 4; nt++) mma16816(acc1[nt], ah1[j], bh1r[j][nt]);
            }
        }
        {
            float* rp = s_red + (8 + warp) * RED_STRIDE;
            #pragma unroll
            for (int nt = 0; nt < 4; nt++) {
                int c0 = (tq * 2) * 4 + nt;
                int c1 = (tq * 2 + 1) * 4 + nt;
                rp[g * 36 + c0]       = acc1[nt][0];
                rp[g * 36 + c1]       = acc1[nt][1];
                rp[(g + 8) * 36 + c0] = acc1[nt][2];
                rp[(g + 8) * 36 + c1] = acc1[nt][3];
            }
        }
        asm volatile("bar.sync 4, 256;" ::: "memory");   // L1 red ready

        // ===== phase 5a (warps 4-7): L1 cell -> h1 -> release f1 -> out =====
        if (cl == 1) {
            float hv1 = 0.f;
            if (s >= 1) {
                float gi = bs0, gf = bs1, gg = bs2, go = bs3;
                const float* rb = s_red + 8 * RED_STRIDE + b * 36 + lu * 4;
                #pragma unroll
                for (int w = 0; w < 8; w++) {
                    float4 v = *(const float4*)&rb[w * RED_STRIDE];
                    gi += v.x; gf += v.y; gg += v.z; go += v.w;
                }
                float fi = sigmoid_ap(gi);
                float ff = sigmoid_ap(gf);
                float fg = tanh_ap(gg);
                float fo = sigmoid_ap(go);
                cc = ff * cc + fi * fg;
                hv1 = fo * tanh_ap(cc);
                unsigned us = (unsigned)__half_as_ushort(__float2half_rn(hv1));
                unsigned other = __shfl_xor_sync(0xffffffffu, us, 16);
                if (lane < 16)
                    g_h1f[(size_t)((s + 1) & 1) * HFRAG_SZ + h_a32] = us | (other << 16);
            }
            asm volatile("bar.sync 5, 128;" ::: "memory");
            if (tid == 128)
                st_release_u32(&g_f1[cblk * FLAG_STRIDE], (unsigned)(s + 1));
            if (s >= 1) {
                out[((size_t)(s - 1) * B_ + b) * H_ + u] = hv1;
                if (nh && s == T_) {
                    nh[B_ * H_ + b * H_ + u] = hv1;
                    nc[B_ * H_ + b * H_ + u] = cc;
                }
            }
        } else {
            // ===== phase 5b (warps 0-3): stage x[s+1]; L0 finals =====
            if (s + 1 < T_) {
                const uint4* xs = (const uint4*)(g_xfrag0 + (size_t)(s + 1) * XFRAG_T);
                #pragma unroll
                for (int i = 0; i < 16; i++)
                    cpa16(A_X + (tid + i*128)*16u, xs + tid + i*128);
            }
            CP_COMMIT; CP_WAIT0;
            if (nh && s == T_ - 1) {
                nh[b * H_ + u] = hv;
                nc[b * H_ + u] = cc;
            }
        }
        __syncthreads();                       // x visible; red reuse safe
    }
}

// ---------------------------------------------------------------------------
extern "C" void kernel_launch(void* const* d_in, const int* in_sizes, int n_in,
                              void* d_out, int out_size) {
    const float* x    = (const float*)d_in[0];
    const float* Wih0 = (const float*)d_in[1];
    const float* bih0 = (const float*)d_in[2];
    const float* Whh0 = (const float*)d_in[3];
    const float* bhh0 = (const float*)d_in[4];
    const float* Wih1 = (const float*)d_in[5];
    const float* bih1 = (const float*)d_in[6];
    const float* Whh1 = (const float*)d_in[7];
    const float* bhh1 = (const float*)d_in[8];
    float* out = (float*)d_out;

    float* nh = nullptr;
    float* nc = nullptr;
    const size_t out1_sz = (size_t)T_ * B_ * H_;
    if ((size_t)out_size >= out1_sz + 4 * B_ * H_) {
        nh = out + out1_sz;
        nc = nh + 2 * B_ * H_;
    }

    static bool attr_done = false;
    if (!attr_done) {
        cudaFuncSetAttribute(k_lstm,
                             cudaFuncAttributeMaxDynamicSharedMemorySize, SMEM_BYTES);
        attr_done = true;
    }

    dim3 gw(2048, 2);
    k_conv_w<<<gw, 256>>>(Wih0, Whh0, Wih1, Whh1);
    k_conv_x<<<4096, 256>>>(x);
    k_reset<<<128, 256>>>();
    k_lstm<<<NCTA, NTHR, SMEM_BYTES>>>(bih0, bhh0, bih1, bhh1, out, nh, nc);
}